// round 13
// baseline (speedup 1.0000x reference)
#include <cuda_runtime.h>
#include <cuda_fp16.h>
#include <cstdint>

// ---------------------------------------------------------------------------
// Problem constants
// ---------------------------------------------------------------------------
#define BATCH   4
#define SEQ     2048
#define DMODEL  1024
#define NHEAD   16
#define HDIM    64
#define MROWS   (BATCH * SEQ)          // 8192
#define QSCALE  0.18033688011112042f   // log2(e) / sqrt(HDIM)

// ---------------------------------------------------------------------------
// Scratch (device globals: allocation-free, graph-capture safe). All fp16.
// ---------------------------------------------------------------------------
__device__ __half g_qh[MROWS * DMODEL];                 // [b,h,s,d] Q (pre-scaled)
__device__ __half g_kh[MROWS * DMODEL];                 // K
__device__ __half g_vh[MROWS * DMODEL];                 // V
__device__ __half g_ax[MROWS * DMODEL];                 // x fp16 [M, K]
__device__ __half g_actxh[MROWS * DMODEL];              // ctx fp16 [M, K]
__device__ __half g_bw[(size_t)3 * DMODEL * DMODEL];    // Wq/Wk/Wv^T fp16 [3][N, K]
__device__ __half g_bwo[(size_t)DMODEL * DMODEL];       // Wo^T fp16 [N, K]

// ---------------------------------------------------------------------------
// PTX helpers — arch-agnostic (sm_80-class) only: harness targets sm_103.
// ---------------------------------------------------------------------------
__device__ __forceinline__ uint32_t smem_u32(const void* p) {
    uint32_t a;
    asm("{ .reg .u64 t; cvta.to.shared.u64 t, %1; cvt.u32.u64 %0, t; }" : "=r"(a) : "l"(p));
    return a;
}
__device__ __forceinline__ void cp_async16(uint32_t dst, const void* src) {
    size_t g = __cvta_generic_to_global(src);
    asm volatile("cp.async.cg.shared.global [%0], [%1], 16;" :: "r"(dst), "l"(g) : "memory");
}
__device__ __forceinline__ void cp_commit() {
    asm volatile("cp.async.commit_group;" ::: "memory");
}
template <int N>
__device__ __forceinline__ void cp_wait() {
    asm volatile("cp.async.wait_group %0;" :: "n"(N) : "memory");
}
__device__ __forceinline__ uint32_t swz(uint32_t b) {   // Swizzle<3,4,3> on 128B rows
    return b ^ ((b >> 3) & 0x70);
}
__device__ __forceinline__ float ex2(float x) {
    float y;
    asm("ex2.approx.ftz.f32 %0, %1;" : "=f"(y) : "f"(x));
    return y;
}
__device__ __forceinline__ uint32_t h2(float a, float b) {
    __half2 h = __floats2half2_rn(a, b);
    return *reinterpret_cast<uint32_t*>(&h);
}

#define MMAH(acc, a, b0, b1)                                                         \
    asm volatile(                                                                    \
        "mma.sync.aligned.m16n8k16.row.col.f32.f16.f16.f32 "                         \
        "{%0,%1,%2,%3}, {%4,%5,%6,%7}, {%8,%9}, {%0,%1,%2,%3};"                      \
        : "+f"((acc)[0]), "+f"((acc)[1]), "+f"((acc)[2]), "+f"((acc)[3])             \
        : "r"((a)[0]), "r"((a)[1]), "r"((a)[2]), "r"((a)[3]), "r"(b0), "r"(b1))

#define LDSM4(r, addr)                                                               \
    asm volatile("ldmatrix.sync.aligned.m8n8.x4.shared.b16 {%0,%1,%2,%3}, [%4];"     \
                 : "=r"((r)[0]), "=r"((r)[1]), "=r"((r)[2]), "=r"((r)[3]) : "r"(addr))

// ---------------------------------------------------------------------------
// Conversions (host-input preprocessing)
// ---------------------------------------------------------------------------
__global__ void split_kernel(const float* __restrict__ in)   // x -> g_ax fp16
{
    int idx = blockIdx.x * 256 + threadIdx.x;     // one float4 per thread
    size_t off = (size_t)idx * 4;
    float4 v = *(const float4*)&in[off];
    uint2 hp;
    hp.x = h2(v.x, v.y);
    hp.y = h2(v.z, v.w);
    *(uint2*)&g_ax[off] = hp;
}

// Weight transpose + fp16 convert: z 0..2 -> g_bw, z==3 -> g_bwo.
__global__ void wsplit_kernel(const float* __restrict__ wq, const float* __restrict__ wk,
                              const float* __restrict__ wv, const float* __restrict__ wo)
{
    const float* W;
    switch (blockIdx.z) {
        case 0: W = wq; break; case 1: W = wk; break;
        case 2: W = wv; break; default: W = wo; break;
    }
    __shared__ float t[32][33];
    int k0 = blockIdx.x * 32, n0 = blockIdx.y * 32;
    int tx = threadIdx.x & 31, ty = threadIdx.x >> 5;
#pragma unroll
    for (int i = 0; i < 4; i++)
        t[ty + i * 8][tx] = W[(size_t)(k0 + ty + i * 8) * DMODEL + n0 + tx];
    __syncthreads();

    __half* out = (blockIdx.z < 3) ? (g_bw + (size_t)blockIdx.z * DMODEL * DMODEL) : g_bwo;
#pragma unroll
    for (int i = 0; i < 4; i++) {
        int nl = ty + i * 8;
        out[(size_t)(n0 + nl) * DMODEL + k0 + tx] = __float2half_rn(t[tx][nl]);
    }
}

// ---------------------------------------------------------------------------
// mma.sync fp16 GEMM, 128x128 CTA tile, BK=64, 3-stage cp.async, 2 CTAs/SM.
// MODE: 0 -> fp32 C+bias. 3 -> fp16 out, head-major [b,h,s,d], scaled.
// ---------------------------------------------------------------------------
#define STAGES 3
#define CHUNK_BYTES 32768
#define GEMM_SMEM (STAGES * CHUNK_BYTES)
#define KDIM DMODEL
#define NCH (KDIM / 64)    // 16

template <int MODE>
__device__ __forceinline__ void gemm_mma_body(const uint16_t* __restrict__ A,
                                              const uint16_t* __restrict__ B,
                                              const float* __restrict__ bias,
                                              float* __restrict__ C,
                                              uint16_t* __restrict__ Oh,
                                              float scale)
{
    extern __shared__ char smem[];
    const uint32_t sbase = smem_u32(smem);
    const int tid  = threadIdx.x;
    const int lane = tid & 31;
    const int w    = tid >> 5;
    const int wm   = w & 1;
    const int wn   = w >> 1;
    const int m0   = blockIdx.y * 128;
    const int n0   = blockIdx.x * 128;

    const uint16_t* Abase = A + (size_t)m0 * KDIM;
    const uint16_t* Bbase = B + (size_t)n0 * KDIM;

    const int r0 = tid >> 3;
    const int u  = tid & 7;

    auto load_chunk = [&](int c) {
        uint32_t so = sbase + (uint32_t)(c % STAGES) * CHUNK_BYTES;
        const uint16_t* as = Abase + (size_t)r0 * KDIM + c * 64 + u * 8;
        const uint16_t* bs = Bbase + (size_t)r0 * KDIM + c * 64 + u * 8;
#pragma unroll
        for (int i = 0; i < 4; i++) {
            uint32_t d = swz((uint32_t)(i * 32 + r0) * 128 + u * 16);
            cp_async16(so + d,         as + (size_t)i * 32 * KDIM);
            cp_async16(so + 16384 + d, bs + (size_t)i * 32 * KDIM);
        }
        cp_commit();
    };

    float acc[4][4][4];
#pragma unroll
    for (int mi = 0; mi < 4; mi++)
#pragma unroll
        for (int ni = 0; ni < 4; ni++)
#pragma unroll
            for (int r = 0; r < 4; r++) acc[mi][ni][r] = 0.f;

    load_chunk(0);
    load_chunk(1);

    for (int c = 0; c < NCH; c++) {
        cp_wait<1>();
        __syncthreads();
        if (c + 2 < NCH) load_chunk(c + 2);

        uint32_t sa = sbase + (uint32_t)(c % STAGES) * CHUNK_BYTES;
        uint32_t sb = sa + 16384;

#pragma unroll
        for (int ks = 0; ks < 4; ks++) {
            uint32_t a[4][4], b[4][2];
#pragma unroll
            for (int mi = 0; mi < 4; mi++) {
                int r = wm * 64 + mi * 16 + (lane & 15);
                uint32_t addr = sa + swz((uint32_t)r * 128 + ks * 32 + (lane >> 4) * 16);
                LDSM4(a[mi], addr);
            }
#pragma unroll
            for (int nj = 0; nj < 2; nj++) {
                int n = wn * 32 + nj * 16 + (lane >> 4) * 8 + (lane & 7);
                uint32_t addr = sb + swz((uint32_t)n * 128 + ks * 32 + ((lane >> 3) & 1) * 16);
                asm volatile("ldmatrix.sync.aligned.m8n8.x4.shared.b16 {%0,%1,%2,%3}, [%4];"
                             : "=r"(b[nj * 2][0]), "=r"(b[nj * 2][1]),
                               "=r"(b[nj * 2 + 1][0]), "=r"(b[nj * 2 + 1][1])
                             : "r"(addr));
            }
#pragma unroll
            for (int mi = 0; mi < 4; mi++)
#pragma unroll
                for (int ni = 0; ni < 4; ni++)
                    MMAH(acc[mi][ni], a[mi], b[ni][0], b[ni][1]);
        }
    }

    const int mrow = m0 + wm * 64 + (lane >> 2);
    const int ncol = n0 + wn * 32 + (lane & 3) * 2;
#pragma unroll
    for (int mi = 0; mi < 4; mi++) {
        int r = mrow + mi * 16;
#pragma unroll
        for (int ni = 0; ni < 4; ni++) {
            int cc = ncol + ni * 8;
            float b0 = bias[cc], b1 = bias[cc + 1];
            float v0 = acc[mi][ni][0] + b0, v1 = acc[mi][ni][1] + b1;
            float v2 = acc[mi][ni][2] + b0, v3 = acc[mi][ni][3] + b1;
            if (MODE == 0) {
                *(float2*)&C[(size_t)r * DMODEL + cc]       = make_float2(v0, v1);
                *(float2*)&C[(size_t)(r + 8) * DMODEL + cc] = make_float2(v2, v3);
            } else {   // MODE 3: fp16, head-major
                v0 *= scale; v1 *= scale; v2 *= scale; v3 *= scale;
                int bb = r >> 11, hh = cc >> 6, dd = cc & 63;
                size_t off0 = (((size_t)bb * NHEAD + hh) * SEQ + (r & 2047)) * HDIM + dd;
                size_t off1 = off0 + 8 * HDIM;
                *(uint32_t*)&Oh[off0] = h2(v0, v1);
                *(uint32_t*)&Oh[off1] = h2(v2, v3);
            }
        }
    }
}

__global__ __launch_bounds__(256, 2) void qkv_tc_kernel(
    const float* __restrict__ bq, const float* __restrict__ bk, const float* __restrict__ bv)
{
    if (blockIdx.z == 0)
        gemm_mma_body<3>((const uint16_t*)g_ax, (const uint16_t*)g_bw,
                         bq, nullptr, (uint16_t*)g_qh, QSCALE);
    else if (blockIdx.z == 1)
        gemm_mma_body<3>((const uint16_t*)g_ax,
                         (const uint16_t*)(g_bw + (size_t)DMODEL * DMODEL),
                         bk, nullptr, (uint16_t*)g_kh, 1.f);
    else
        gemm_mma_body<3>((const uint16_t*)g_ax,
                         (const uint16_t*)(g_bw + (size_t)2 * DMODEL * DMODEL),
                         bv, nullptr, (uint16_t*)g_vh, 1.f);
}

__global__ __launch_bounds__(256, 2) void out_tc_kernel(
    const float* __restrict__ bo, float* __restrict__ out)
{
    gemm_mma_body<0>((const uint16_t*)g_actxh, (const uint16_t*)g_bwo,
                     bo, out, nullptr, 1.f);
}

// ---------------------------------------------------------------------------
// Tensor-core causal flash attention, software-pipelined.
// 128 threads (4 warps), q-tile 64, k-tile 64, 3 CTAs/SM.
// QK^T of tile kt+1 is issued between the softmax max-reduction and the
// exp/PV of tile kt, hiding the serial softmax chain behind independent MMAs.
// K/V triple-buffered (mod 3) so the kt+2 prefetch never collides.
// Smem: Q (8KB) + 3 x (Kh|Vh) (3x16KB) = 56KB.
// ---------------------------------------------------------------------------
#define ATT_SMEM 57344

__global__ __launch_bounds__(128, 3) void attn_tc_kernel()
{
    extern __shared__ char smem[];
    const uint32_t sb = smem_u32(smem);
    const int tid  = threadIdx.x;
    const int lane = tid & 31;
    const int w    = tid >> 5;                            // 0..3
    const int qt   = (int)(gridDim.x - 1 - blockIdx.x);   // heavy tiles first
    const int h    = blockIdx.y, b = blockIdx.z;
    const int q0   = qt * 64;
    const int nkt  = qt + 1;
    const size_t bh = ((size_t)b * NHEAD + h) * SEQ * HDIM;
    const __half *Qhp = g_qh + bh;
    const __half *Khp = g_kh + bh;
    const __half *Vhp = g_vh + bh;

    const int u   = tid & 7;
    const int r16 = tid >> 3;        // 0..15

    // ---- stage Q (q0..q0+63)  [group]
#pragma unroll
    for (int i = 0; i < 4; i++) {
        int row = r16 + 16 * i;
        uint32_t d = swz((uint32_t)row * 128 + u * 16);
        cp_async16(sb + d, Qhp + (size_t)(q0 + row) * HDIM + u * 8);
    }
    cp_commit();

    auto load_kv = [&](int kt) {
        uint32_t so = sb + 8192 + (uint32_t)(kt % 3) * 16384;
        int kbase = kt * 64;
#pragma unroll
        for (int i = 0; i < 4; i++) {
            int row = r16 + 16 * i;
            uint32_t d = swz((uint32_t)row * 128 + u * 16);
            size_t g = (size_t)(kbase + row) * HDIM + u * 8;
            cp_async16(so + d,        Khp + g);
            cp_async16(so + 8192 + d, Vhp + g);
        }
        cp_commit();
    };

    load_kv(0);
    if (nkt > 1) { load_kv(1); cp_wait<1>(); }
    else         { cp_wait<0>(); }
    __syncthreads();

    // ---- resident Q fragments (warp w owns rows w*16..w*16+15)
    uint32_t qh[4][4];
#pragma unroll
    for (int ks = 0; ks < 4; ks++) {
        uint32_t d = swz((uint32_t)(w * 16 + (lane & 15)) * 128 + ks * 32 + (lane >> 4) * 16);
        LDSM4(qh[ks], sb + d);
    }

    // S = Q K^T for one k-tile from KV buffer (kt%3), optional causal mask.
    auto compute_qk = [&](float (&s)[8][4], int kt) {
        const uint32_t sk = sb + 8192 + (uint32_t)(kt % 3) * 16384;
#pragma unroll
        for (int nt = 0; nt < 8; nt++) {
            s[nt][0] = s[nt][1] = s[nt][2] = s[nt][3] = 0.f;
            uint32_t kh[4][2];
#pragma unroll
            for (int hf = 0; hf < 2; hf++) {
                uint32_t d = swz((uint32_t)(nt * 8 + (lane & 7)) * 128 + hf * 64 + (lane >> 3) * 16);
                asm volatile("ldmatrix.sync.aligned.m8n8.x4.shared.b16 {%0,%1,%2,%3}, [%4];"
                             : "=r"(kh[2*hf][0]), "=r"(kh[2*hf][1]),
                               "=r"(kh[2*hf+1][0]), "=r"(kh[2*hf+1][1]) : "r"(sk + d));
            }
#pragma unroll
            for (int ks = 0; ks < 4; ks++)
                MMAH(s[nt], qh[ks], kh[ks][0], kh[ks][1]);
        }
        if (kt == nkt - 1) {          // only the final tile crosses the diagonal
            int qr = q0 + w * 16 + (lane >> 2);
#pragma unroll
            for (int nt = 0; nt < 8; nt++) {
                int kc = kt * 64 + nt * 8 + (lane & 3) * 2;
                if (kc     > qr)     s[nt][0] = -1e30f;
                if (kc + 1 > qr)     s[nt][1] = -1e30f;
                if (kc     > qr + 8) s[nt][2] = -1e30f;
                if (kc + 1 > qr + 8) s[nt][3] = -1e30f;
            }
        }
    };

    float s[8][4], s2[8][4];
    compute_qk(s, 0);

    float ctx[8][4];
#pragma unroll
    for (int dt = 0; dt < 8; dt++)
#pragma unroll
        for (int r = 0; r < 4; r++) ctx[dt][r] = 0.f;
    float m0 = -1e30f, m1 = -1e30f, l0 = 0.f, l1 = 0.f;

    for (int kt = 0; kt < nkt; kt++) {
        // ---- row max of current tile (serial shfl chain starts early)
        float mx0 = -1e30f, mx1 = -1e30f;
#pragma unroll
        for (int nt = 0; nt < 8; nt++) {
            mx0 = fmaxf(mx0, fmaxf(s[nt][0], s[nt][1]));
            mx1 = fmaxf(mx1, fmaxf(s[nt][2], s[nt][3]));
        }
        mx0 = fmaxf(mx0, __shfl_xor_sync(0xffffffffu, mx0, 1));
        mx0 = fmaxf(mx0, __shfl_xor_sync(0xffffffffu, mx0, 2));
        mx1 = fmaxf(mx1, __shfl_xor_sync(0xffffffffu, mx1, 1));
        mx1 = fmaxf(mx1, __shfl_xor_sync(0xffffffffu, mx1, 2));

        // ---- overlap: QK of next tile (independent of softmax chain)
        if (kt + 1 < nkt) {
            cp_wait<0>();            // tile kt+1 resident
            __syncthreads();         // all warps past PV(kt-1) -> buf (kt+2)%3 free
            if (kt + 2 < nkt) load_kv(kt + 2);
            compute_qk(s2, kt + 1);
        }

        // ---- softmax update for current tile
        float mn0 = fmaxf(m0, mx0), mn1 = fmaxf(m1, mx1);
        float c0 = ex2(m0 - mn0), c1 = ex2(m1 - mn1);
        m0 = mn0; m1 = mn1;
        l0 *= c0; l1 *= c1;
#pragma unroll
        for (int dt = 0; dt < 8; dt++) {
            ctx[dt][0] *= c0; ctx[dt][1] *= c0;
            ctx[dt][2] *= c1; ctx[dt][3] *= c1;
        }

        // ---- exp, pack P fp16, PV = P Vh  (V from buffer kt%3)
        const uint32_t sv = sb + 8192 + (uint32_t)(kt % 3) * 16384 + 8192;
#pragma unroll
        for (int j = 0; j < 4; j++) {
            float p00 = ex2(s[2*j][0] - mn0),   p01 = ex2(s[2*j][1] - mn0);
            float p02 = ex2(s[2*j][2] - mn1),   p03 = ex2(s[2*j][3] - mn1);
            float p10 = ex2(s[2*j+1][0] - mn0), p11 = ex2(s[2*j+1][1] - mn0);
            float p12 = ex2(s[2*j+1][2] - mn1), p13 = ex2(s[2*j+1][3] - mn1);
            l0 += (p00 + p01) + (p10 + p11);
            l1 += (p02 + p03) + (p12 + p13);
            uint32_t ph[4];
            ph[0] = h2(p00, p01);
            ph[1] = h2(p02, p03);
            ph[2] = h2(p10, p11);
            ph[3] = h2(p12, p13);

            uint32_t vf[8][2];
#pragma unroll
            for (int dp = 0; dp < 4; dp++) {
                uint32_t d = swz((uint32_t)(j * 16 + (lane & 15)) * 128 + dp * 32 + (lane >> 4) * 16);
                asm volatile("ldmatrix.sync.aligned.m8n8.x4.trans.shared.b16 {%0,%1,%2,%3}, [%4];"
                             : "=r"(vf[2*dp][0]), "=r"(vf[2*dp][1]),
                               "=r"(vf[2*dp+1][0]), "=r"(vf[2*dp+1][1]) : "r"(sv + d));
            }
#pragma unroll
            for (int dt = 0; dt < 8; dt++)
                MMAH(ctx[dt], ph, vf[dt][0], vf[dt][1]);
        }

        // ---- rotate score buffers
        if (kt + 1 < nkt) {
#pragma unroll
            for (int nt = 0; nt < 8; nt++)
#pragma unroll
                for (int r = 0; r < 4; r++) s[nt][r] = s2[nt][r];
        }
    }

    // ---- finalize: row sums, normalize, store ctx fp16 [M, DMODEL]
    l0 += __shfl_xor_sync(0xffffffffu, l0, 1);
    l0 += __shfl_xor_sync(0xffffffffu, l0, 2);
    l1 += __shfl_xor_sync(0xffffffffu, l1, 1);
    l1 += __shfl_xor_sync(0xffffffffu, l1, 2);
    float rinv0 = 1.f / l0, rinv1 = 1.f / l1;

    int qr = q0 + w * 16 + (lane >> 2);
    size_t row0 = ((size_t)b * SEQ + qr) * DMODEL;
    size_t row1 = row0 + 8 * DMODEL;
    int cbase = h * HDIM + (lane & 3) * 2;
#pragma unroll
    for (int dt = 0; dt < 8; dt++) {
        int cc = cbase + dt * 8;
        *(uint32_t*)&g_actxh[row0 + cc] = h2(ctx[dt][0] * rinv0, ctx[dt][1] * rinv0);
        *(uint32_t*)&g_actxh[row1 + cc] = h2(ctx[dt][2] * rinv1, ctx[dt][3] * rinv1);
    }
}

// ---------------------------------------------------------------------------
// Launch
// ---------------------------------------------------------------------------
extern "C" void kernel_launch(void* const* d_in, const int* in_sizes, int n_in,
                              void* d_out, int out_size)
{
    const float* x  = (const float*)d_in[0];
    const float* wq = (const float*)d_in[1];
    const float* bq = (const float*)d_in[2];
    const float* wk = (const float*)d_in[3];
    const float* bk = (const float*)d_in[4];
    const float* wv = (const float*)d_in[5];
    const float* bv = (const float*)d_in[6];
    const float* wo = (const float*)d_in[7];
    const float* bo = (const float*)d_in[8];
    float* out = (float*)d_out;
    (void)in_sizes; (void)n_in; (void)out_size;

    cudaFuncSetAttribute(qkv_tc_kernel, cudaFuncAttributeMaxDynamicSharedMemorySize, GEMM_SMEM);
    cudaFuncSetAttribute(out_tc_kernel, cudaFuncAttributeMaxDynamicSharedMemorySize, GEMM_SMEM);
    cudaFuncSetAttribute(attn_tc_kernel, cudaFuncAttributeMaxDynamicSharedMemorySize, ATT_SMEM);

    wsplit_kernel<<<dim3(32, 32, 4), 256>>>(wq, wk, wv, wo);
    split_kernel<<<MROWS * DMODEL / 4 / 256, 256>>>(x);
    qkv_tc_kernel<<<dim3(DMODEL / 128, MROWS / 128, 3), 256, GEMM_SMEM>>>(bq, bk, bv);
    attn_tc_kernel<<<dim3(SEQ / 64, NHEAD, BATCH), 128, ATT_SMEM>>>();
    out_tc_kernel<<<dim3(DMODEL / 128, MROWS / 128), 256, GEMM_SMEM>>>(bo, out);
}

// round 14
// speedup vs baseline: 1.0466x; 1.0466x over previous
#include <cuda_runtime.h>
#include <cuda_fp16.h>
#include <cstdint>

// ---------------------------------------------------------------------------
// Problem constants
// ---------------------------------------------------------------------------
#define BATCH   4
#define SEQ     2048
#define DMODEL  1024
#define NHEAD   16
#define HDIM    64
#define MROWS   (BATCH * SEQ)          // 8192
#define QSCALE  0.18033688011112042f   // log2(e) / sqrt(HDIM)

// ---------------------------------------------------------------------------
// Scratch (device globals: allocation-free, graph-capture safe). All fp16.
// Natural [M, D] layout everywhere: a head's slice (h*64..h*64+63) of a row
// is a contiguous, 128B-aligned line, so attention can cp.async it directly.
// ---------------------------------------------------------------------------
__device__ __half g_qh[MROWS * DMODEL];                 // Q (pre-scaled) [M, D]
__device__ __half g_kh[MROWS * DMODEL];                 // K [M, D]
__device__ __half g_vh[MROWS * DMODEL];                 // V [M, D]
__device__ __half g_ax[MROWS * DMODEL];                 // x fp16 [M, D]
__device__ __half g_actxh[MROWS * DMODEL];              // ctx fp16 [M, D]
__device__ __half g_bw[(size_t)3 * DMODEL * DMODEL];    // Wq/Wk/Wv^T fp16 [3][N, K]
__device__ __half g_bwo[(size_t)DMODEL * DMODEL];       // Wo^T fp16 [N, K]

// ---------------------------------------------------------------------------
// PTX helpers — arch-agnostic (sm_80-class) only: harness targets sm_103.
// ---------------------------------------------------------------------------
__device__ __forceinline__ uint32_t smem_u32(const void* p) {
    uint32_t a;
    asm("{ .reg .u64 t; cvta.to.shared.u64 t, %1; cvt.u32.u64 %0, t; }" : "=r"(a) : "l"(p));
    return a;
}
__device__ __forceinline__ void cp_async16(uint32_t dst, const void* src) {
    size_t g = __cvta_generic_to_global(src);
    asm volatile("cp.async.cg.shared.global [%0], [%1], 16;" :: "r"(dst), "l"(g) : "memory");
}
__device__ __forceinline__ void cp_commit() {
    asm volatile("cp.async.commit_group;" ::: "memory");
}
template <int N>
__device__ __forceinline__ void cp_wait() {
    asm volatile("cp.async.wait_group %0;" :: "n"(N) : "memory");
}
__device__ __forceinline__ uint32_t swz(uint32_t b) {   // Swizzle<3,4,3> on 128B rows
    return b ^ ((b >> 3) & 0x70);
}
__device__ __forceinline__ float ex2(float x) {
    float y;
    asm("ex2.approx.ftz.f32 %0, %1;" : "=f"(y) : "f"(x));
    return y;
}
__device__ __forceinline__ uint32_t h2(float a, float b) {
    __half2 h = __floats2half2_rn(a, b);
    return *reinterpret_cast<uint32_t*>(&h);
}

#define MMAH(acc, a, b0, b1)                                                         \
    asm volatile(                                                                    \
        "mma.sync.aligned.m16n8k16.row.col.f32.f16.f16.f32 "                         \
        "{%0,%1,%2,%3}, {%4,%5,%6,%7}, {%8,%9}, {%0,%1,%2,%3};"                      \
        : "+f"((acc)[0]), "+f"((acc)[1]), "+f"((acc)[2]), "+f"((acc)[3])             \
        : "r"((a)[0]), "r"((a)[1]), "r"((a)[2]), "r"((a)[3]), "r"(b0), "r"(b1))

#define LDSM4(r, addr)                                                               \
    asm volatile("ldmatrix.sync.aligned.m8n8.x4.shared.b16 {%0,%1,%2,%3}, [%4];"     \
                 : "=r"((r)[0]), "=r"((r)[1]), "=r"((r)[2]), "=r"((r)[3]) : "r"(addr))

// ---------------------------------------------------------------------------
// Combined preprocessing: one launch.
// grid (32,32,12): z 0..3  -> weight transpose + fp16 convert
//                  z 4..11 -> x fp32 -> fp16 (8 planes x 1024 blocks x 1024 elems)
// ---------------------------------------------------------------------------
__global__ void prep_kernel(const float* __restrict__ x,
                            const float* __restrict__ wq, const float* __restrict__ wk,
                            const float* __restrict__ wv, const float* __restrict__ wo)
{
    if (blockIdx.z >= 4) {
        int blk = (blockIdx.z - 4) * 1024 + blockIdx.y * 32 + blockIdx.x;
        size_t off = ((size_t)blk * 256 + threadIdx.x) * 4;
        float4 v = *(const float4*)&x[off];
        uint2 hp;
        hp.x = h2(v.x, v.y);
        hp.y = h2(v.z, v.w);
        *(uint2*)&g_ax[off] = hp;
        return;
    }

    const float* W;
    switch (blockIdx.z) {
        case 0: W = wq; break; case 1: W = wk; break;
        case 2: W = wv; break; default: W = wo; break;
    }
    __shared__ float t[32][33];
    int k0 = blockIdx.x * 32, n0 = blockIdx.y * 32;
    int tx = threadIdx.x & 31, ty = threadIdx.x >> 5;
#pragma unroll
    for (int i = 0; i < 4; i++)
        t[ty + i * 8][tx] = W[(size_t)(k0 + ty + i * 8) * DMODEL + n0 + tx];
    __syncthreads();

    __half* out = (blockIdx.z < 3) ? (g_bw + (size_t)blockIdx.z * DMODEL * DMODEL) : g_bwo;
#pragma unroll
    for (int i = 0; i < 4; i++) {
        int nl = ty + i * 8;
        out[(size_t)(n0 + nl) * DMODEL + k0 + tx] = __float2half_rn(t[tx][nl]);
    }
}

// ---------------------------------------------------------------------------
// mma.sync fp16 GEMM, 128x128 CTA tile, BK=64, 3-stage cp.async, 2 CTAs/SM.
// MODE: 0 -> fp32 C+bias. 3 -> fp16 out [M, D] natural layout, scaled.
// ---------------------------------------------------------------------------
#define STAGES 3
#define CHUNK_BYTES 32768
#define GEMM_SMEM (STAGES * CHUNK_BYTES)
#define KDIM DMODEL
#define NCH (KDIM / 64)    // 16

template <int MODE>
__device__ __forceinline__ void gemm_mma_body(const uint16_t* __restrict__ A,
                                              const uint16_t* __restrict__ B,
                                              const float* __restrict__ bias,
                                              float* __restrict__ C,
                                              uint16_t* __restrict__ Oh,
                                              float scale)
{
    extern __shared__ char smem[];
    const uint32_t sbase = smem_u32(smem);
    const int tid  = threadIdx.x;
    const int lane = tid & 31;
    const int w    = tid >> 5;
    const int wm   = w & 1;
    const int wn   = w >> 1;
    const int m0   = blockIdx.y * 128;
    const int n0   = blockIdx.x * 128;

    const uint16_t* Abase = A + (size_t)m0 * KDIM;
    const uint16_t* Bbase = B + (size_t)n0 * KDIM;

    const int r0 = tid >> 3;
    const int u  = tid & 7;

    auto load_chunk = [&](int c) {
        uint32_t so = sbase + (uint32_t)(c % STAGES) * CHUNK_BYTES;
        const uint16_t* as = Abase + (size_t)r0 * KDIM + c * 64 + u * 8;
        const uint16_t* bs = Bbase + (size_t)r0 * KDIM + c * 64 + u * 8;
#pragma unroll
        for (int i = 0; i < 4; i++) {
            uint32_t d = swz((uint32_t)(i * 32 + r0) * 128 + u * 16);
            cp_async16(so + d,         as + (size_t)i * 32 * KDIM);
            cp_async16(so + 16384 + d, bs + (size_t)i * 32 * KDIM);
        }
        cp_commit();
    };

    float acc[4][4][4];
#pragma unroll
    for (int mi = 0; mi < 4; mi++)
#pragma unroll
        for (int ni = 0; ni < 4; ni++)
#pragma unroll
            for (int r = 0; r < 4; r++) acc[mi][ni][r] = 0.f;

    load_chunk(0);
    load_chunk(1);

    for (int c = 0; c < NCH; c++) {
        cp_wait<1>();
        __syncthreads();
        if (c + 2 < NCH) load_chunk(c + 2);

        uint32_t sa = sbase + (uint32_t)(c % STAGES) * CHUNK_BYTES;
        uint32_t sb = sa + 16384;

#pragma unroll
        for (int ks = 0; ks < 4; ks++) {
            uint32_t a[4][4], b[4][2];
#pragma unroll
            for (int mi = 0; mi < 4; mi++) {
                int r = wm * 64 + mi * 16 + (lane & 15);
                uint32_t addr = sa + swz((uint32_t)r * 128 + ks * 32 + (lane >> 4) * 16);
                LDSM4(a[mi], addr);
            }
#pragma unroll
            for (int nj = 0; nj < 2; nj++) {
                int n = wn * 32 + nj * 16 + (lane >> 4) * 8 + (lane & 7);
                uint32_t addr = sb + swz((uint32_t)n * 128 + ks * 32 + ((lane >> 3) & 1) * 16);
                asm volatile("ldmatrix.sync.aligned.m8n8.x4.shared.b16 {%0,%1,%2,%3}, [%4];"
                             : "=r"(b[nj * 2][0]), "=r"(b[nj * 2][1]),
                               "=r"(b[nj * 2 + 1][0]), "=r"(b[nj * 2 + 1][1])
                             : "r"(addr));
            }
#pragma unroll
            for (int mi = 0; mi < 4; mi++)
#pragma unroll
                for (int ni = 0; ni < 4; ni++)
                    MMAH(acc[mi][ni], a[mi], b[ni][0], b[ni][1]);
        }
    }

    const int mrow = m0 + wm * 64 + (lane >> 2);
    const int ncol = n0 + wn * 32 + (lane & 3) * 2;
#pragma unroll
    for (int mi = 0; mi < 4; mi++) {
        int r = mrow + mi * 16;
#pragma unroll
        for (int ni = 0; ni < 4; ni++) {
            int cc = ncol + ni * 8;
            float b0 = bias[cc], b1 = bias[cc + 1];
            float v0 = acc[mi][ni][0] + b0, v1 = acc[mi][ni][1] + b1;
            float v2 = acc[mi][ni][2] + b0, v3 = acc[mi][ni][3] + b1;
            if (MODE == 0) {
                *(float2*)&C[(size_t)r * DMODEL + cc]       = make_float2(v0, v1);
                *(float2*)&C[(size_t)(r + 8) * DMODEL + cc] = make_float2(v2, v3);
            } else {   // MODE 3: fp16, natural [M, D]
                v0 *= scale; v1 *= scale; v2 *= scale; v3 *= scale;
                *(uint32_t*)&Oh[(size_t)r * DMODEL + cc]       = h2(v0, v1);
                *(uint32_t*)&Oh[(size_t)(r + 8) * DMODEL + cc] = h2(v2, v3);
            }
        }
    }
}

__global__ __launch_bounds__(256, 2) void qkv_tc_kernel(
    const float* __restrict__ bq, const float* __restrict__ bk, const float* __restrict__ bv)
{
    if (blockIdx.z == 0)
        gemm_mma_body<3>((const uint16_t*)g_ax, (const uint16_t*)g_bw,
                         bq, nullptr, (uint16_t*)g_qh, QSCALE);
    else if (blockIdx.z == 1)
        gemm_mma_body<3>((const uint16_t*)g_ax,
                         (const uint16_t*)(g_bw + (size_t)DMODEL * DMODEL),
                         bk, nullptr, (uint16_t*)g_kh, 1.f);
    else
        gemm_mma_body<3>((const uint16_t*)g_ax,
                         (const uint16_t*)(g_bw + (size_t)2 * DMODEL * DMODEL),
                         bv, nullptr, (uint16_t*)g_vh, 1.f);
}

__global__ __launch_bounds__(256, 2) void out_tc_kernel(
    const float* __restrict__ bo, float* __restrict__ out)
{
    gemm_mma_body<0>((const uint16_t*)g_actxh, (const uint16_t*)g_bwo,
                     bo, out, nullptr, 1.f);
}

// ---------------------------------------------------------------------------
// Tensor-core causal flash attention (round-12 structure, natural layout).
// 128 threads (4 warps), q-tile 64, k-tile 64, 4 CTAs/SM.
// Q/K/V rows are read from [M, D] with column offset h*HDIM (contiguous 128B).
// Smem: Q (8KB) + 2 x (Kh|Vh) (2x16KB) = 40KB.
// ---------------------------------------------------------------------------
#define ATT_SMEM 40960

__global__ __launch_bounds__(128, 4) void attn_tc_kernel()
{
    extern __shared__ char smem[];
    const uint32_t sb = smem_u32(smem);
    const int tid  = threadIdx.x;
    const int lane = tid & 31;
    const int w    = tid >> 5;                            // 0..3
    const int qt   = (int)(gridDim.x - 1 - blockIdx.x);   // heavy tiles first
    const int h    = blockIdx.y, b = blockIdx.z;
    const int q0   = qt * 64;
    const int nkt  = qt + 1;
    // natural [M, D]: base points at column h*HDIM of row b*SEQ
    const size_t bh = (size_t)b * SEQ * DMODEL + (size_t)h * HDIM;
    const __half *Qhp = g_qh + bh;
    const __half *Khp = g_kh + bh;
    const __half *Vhp = g_vh + bh;

    const int u   = tid & 7;
    const int r16 = tid >> 3;        // 0..15

    // ---- stage Q (q0..q0+63): 64 rows x 8 units / 128 thr = 4 per thread
#pragma unroll
    for (int i = 0; i < 4; i++) {
        int row = r16 + 16 * i;
        uint32_t d = swz((uint32_t)row * 128 + u * 16);
        cp_async16(sb + d, Qhp + (size_t)(q0 + row) * DMODEL + u * 8);
    }
    cp_commit();

    auto load_kv = [&](int kt) {
        uint32_t so = sb + 8192 + (uint32_t)(kt & 1) * 16384;
        int kbase = kt * 64;
#pragma unroll
        for (int i = 0; i < 4; i++) {
            int row = r16 + 16 * i;
            uint32_t d = swz((uint32_t)row * 128 + u * 16);
            size_t g = (size_t)(kbase + row) * DMODEL + u * 8;
            cp_async16(so + d,        Khp + g);
            cp_async16(so + 8192 + d, Vhp + g);
        }
        cp_commit();
    };
    load_kv(0);
    cp_wait<0>();
    __syncthreads();

    // ---- resident Q fragments (warp w owns rows w*16..w*16+15)
    uint32_t qh[4][4];
#pragma unroll
    for (int ks = 0; ks < 4; ks++) {
        uint32_t d = swz((uint32_t)(w * 16 + (lane & 15)) * 128 + ks * 32 + (lane >> 4) * 16);
        LDSM4(qh[ks], sb + d);
    }

    float ctx[8][4];
#pragma unroll
    for (int dt = 0; dt < 8; dt++)
#pragma unroll
        for (int r = 0; r < 4; r++) ctx[dt][r] = 0.f;
    float m0 = -1e30f, m1 = -1e30f, l0 = 0.f, l1 = 0.f;

    for (int kt = 0; kt < nkt; kt++) {
        cp_wait<0>();
        __syncthreads();
        if (kt + 1 < nkt) load_kv(kt + 1);
        const uint32_t sk = sb + 8192 + (uint32_t)(kt & 1) * 16384;

        // ---- S = Q K^T  (single fp16 term)
        float s[8][4];
#pragma unroll
        for (int nt = 0; nt < 8; nt++) {
            s[nt][0] = s[nt][1] = s[nt][2] = s[nt][3] = 0.f;
            uint32_t kh[4][2];
#pragma unroll
            for (int hf = 0; hf < 2; hf++) {
                uint32_t d = swz((uint32_t)(nt * 8 + (lane & 7)) * 128 + hf * 64 + (lane >> 3) * 16);
                asm volatile("ldmatrix.sync.aligned.m8n8.x4.shared.b16 {%0,%1,%2,%3}, [%4];"
                             : "=r"(kh[2*hf][0]), "=r"(kh[2*hf][1]),
                               "=r"(kh[2*hf+1][0]), "=r"(kh[2*hf+1][1]) : "r"(sk + d));
            }
#pragma unroll
            for (int ks = 0; ks < 4; ks++)
                MMAH(s[nt], qh[ks], kh[ks][0], kh[ks][1]);
        }

        // ---- causal mask (only the final k-tile crosses the diagonal)
        if (kt == nkt - 1) {
            int qr = q0 + w * 16 + (lane >> 2);
#pragma unroll
            for (int nt = 0; nt < 8; nt++) {
                int kc = kt * 64 + nt * 8 + (lane & 3) * 2;
                if (kc     > qr)     s[nt][0] = -1e30f;
                if (kc + 1 > qr)     s[nt][1] = -1e30f;
                if (kc     > qr + 8) s[nt][2] = -1e30f;
                if (kc + 1 > qr + 8) s[nt][3] = -1e30f;
            }
        }

        // ---- online softmax (exp2 domain)
        float mx0 = -1e30f, mx1 = -1e30f;
#pragma unroll
        for (int nt = 0; nt < 8; nt++) {
            mx0 = fmaxf(mx0, fmaxf(s[nt][0], s[nt][1]));
            mx1 = fmaxf(mx1, fmaxf(s[nt][2], s[nt][3]));
        }
        mx0 = fmaxf(mx0, __shfl_xor_sync(0xffffffffu, mx0, 1));
        mx0 = fmaxf(mx0, __shfl_xor_sync(0xffffffffu, mx0, 2));
        mx1 = fmaxf(mx1, __shfl_xor_sync(0xffffffffu, mx1, 1));
        mx1 = fmaxf(mx1, __shfl_xor_sync(0xffffffffu, mx1, 2));
        float mn0 = fmaxf(m0, mx0), mn1 = fmaxf(m1, mx1);
        float c0 = ex2(m0 - mn0), c1 = ex2(m1 - mn1);
        m0 = mn0; m1 = mn1;
        l0 *= c0; l1 *= c1;
#pragma unroll
        for (int dt = 0; dt < 8; dt++) {
            ctx[dt][0] *= c0; ctx[dt][1] *= c0;
            ctx[dt][2] *= c1; ctx[dt][3] *= c1;
        }

        // ---- per-j: exp, pack P fp16, PV = P Vh
        const uint32_t sv = sk + 8192;
#pragma unroll
        for (int j = 0; j < 4; j++) {
            float p00 = ex2(s[2*j][0] - mn0),   p01 = ex2(s[2*j][1] - mn0);
            float p02 = ex2(s[2*j][2] - mn1),   p03 = ex2(s[2*j][3] - mn1);
            float p10 = ex2(s[2*j+1][0] - mn0), p11 = ex2(s[2*j+1][1] - mn0);
            float p12 = ex2(s[2*j+1][2] - mn1), p13 = ex2(s[2*j+1][3] - mn1);
            l0 += (p00 + p01) + (p10 + p11);
            l1 += (p02 + p03) + (p12 + p13);
            uint32_t ph[4];
            ph[0] = h2(p00, p01);
            ph[1] = h2(p02, p03);
            ph[2] = h2(p10, p11);
            ph[3] = h2(p12, p13);

            uint32_t vf[8][2];
#pragma unroll
            for (int dp = 0; dp < 4; dp++) {
                uint32_t d = swz((uint32_t)(j * 16 + (lane & 15)) * 128 + dp * 32 + (lane >> 4) * 16);
                asm volatile("ldmatrix.sync.aligned.m8n8.x4.trans.shared.b16 {%0,%1,%2,%3}, [%4];"
                             : "=r"(vf[2*dp][0]), "=r"(vf[2*dp][1]),
                               "=r"(vf[2*dp+1][0]), "=r"(vf[2*dp+1][1]) : "r"(sv + d));
            }
#pragma unroll
            for (int dt = 0; dt < 8; dt++)
                MMAH(ctx[dt], ph, vf[dt][0], vf[dt][1]);
        }
    }

    // ---- finalize: row sums, normalize, store ctx fp16 [M, D]
    l0 += __shfl_xor_sync(0xffffffffu, l0, 1);
    l0 += __shfl_xor_sync(0xffffffffu, l0, 2);
    l1 += __shfl_xor_sync(0xffffffffu, l1, 1);
    l1 += __shfl_xor_sync(0xffffffffu, l1, 2);
    float rinv0 = 1.f / l0, rinv1 = 1.f / l1;

    int qr = q0 + w * 16 + (lane >> 2);
    size_t row0 = ((size_t)b * SEQ + qr) * DMODEL;
    size_t row1 = row0 + 8 * DMODEL;
    int cbase = h * HDIM + (lane & 3) * 2;
#pragma unroll
    for (int dt = 0; dt < 8; dt++) {
        int cc = cbase + dt * 8;
        *(uint32_t*)&g_actxh[row0 + cc] = h2(ctx[dt][0] * rinv0, ctx[dt][1] * rinv0);
        *(uint32_t*)&g_actxh[row1 + cc] = h2(ctx[dt][2] * rinv1, ctx[dt][3] * rinv1);
    }
}

// ---------------------------------------------------------------------------
// Launch
// ---------------------------------------------------------------------------
extern "C" void kernel_launch(void* const* d_in, const int* in_sizes, int n_in,
                              void* d_out, int out_size)
{
    const float* x  = (const float*)d_in[0];
    const float* wq = (const float*)d_in[1];
    const float* bq = (const float*)d_in[2];
    const float* wk = (const float*)d_in[3];
    const float* bk = (const float*)d_in[4];
    const float* wv = (const float*)d_in[5];
    const float* bv = (const float*)d_in[6];
    const float* wo = (const float*)d_in[7];
    const float* bo = (const float*)d_in[8];
    float* out = (float*)d_out;
    (void)in_sizes; (void)n_in; (void)out_size;

    cudaFuncSetAttribute(qkv_tc_kernel, cudaFuncAttributeMaxDynamicSharedMemorySize, GEMM_SMEM);
    cudaFuncSetAttribute(out_tc_kernel, cudaFuncAttributeMaxDynamicSharedMemorySize, GEMM_SMEM);
    cudaFuncSetAttribute(attn_tc_kernel, cudaFuncAttributeMaxDynamicSharedMemorySize, ATT_SMEM);

    // Combined weight-convert + x-convert (single launch).
    prep_kernel<<<dim3(32, 32, 12), 256>>>(x, wq, wk, wv, wo);
    qkv_tc_kernel<<<dim3(DMODEL / 128, MROWS / 128, 3), 256, GEMM_SMEM>>>(bq, bk, bv);
    attn_tc_kernel<<<dim3(SEQ / 64, NHEAD, BATCH), 128, ATT_SMEM>>>();
    out_tc_kernel<<<dim3(DMODEL / 128, MROWS / 128), 256, GEMM_SMEM>>>(bo, out);
}